// round 1
// baseline (speedup 1.0000x reference)
#include <cuda_runtime.h>
#include <cstdint>

// DangoCutouts: 16 x (3,512,512) fp32 outputs from one (3,4096,4096) image.
//   img 0: full 4096->512 bilinear downsample (color)
//   img 1: gray(full)
//   img 2: full, x-flipped
//   img 3: gray(flipped)
//   img 4..15: random crops (offy/offx/sizes), img 4 grayed.

#define H 4096
#define W 4096
#define CUT 512
#define CH_STRIDE (4096u * 4096u)

__global__ __launch_bounds__(256)
void dango_cutouts_kernel(const float* __restrict__ img,
                          const int*   __restrict__ sizes,
                          const int*   __restrict__ offy,
                          const int*   __restrict__ offx,
                          float*       __restrict__ out)
{
    const int p  = blockIdx.x * blockDim.x + threadIdx.x;   // 0 .. 512*512-1
    const int im = blockIdx.y;                               // 0 .. 15
    const int yo = p >> 9;
    const int xo = p & 511;

    int oy, ox, size;
    bool gray, flip;
    if (im < 4) {
        oy = 0; ox = 0; size = 4096;
        gray = (im & 1);
        flip = (im >= 2);
    } else {
        const int j = im - 4;
        oy   = __ldg(offy  + j);
        ox   = __ldg(offx  + j);
        size = __ldg(sizes + j);
        gray = (j == 0);
        flip = false;
    }

    const int xs = flip ? (511 - xo) : xo;

    const float s  = (float)size;
    const float sc = s * (1.0f / 512.0f);   // exact power-of-two scale

    // y coordinate (matches jax: t=(i+0.5)*s/512-0.5; y=clip(oy+t, oy, oy+s-1))
    float ty = ((float)yo + 0.5f) * sc - 0.5f;
    float yf = (float)oy + ty;
    yf = fminf(fmaxf(yf, (float)oy), (float)oy + s - 1.0f);
    int   y0 = (int)floorf(yf);
    int   y1 = min(y0 + 1, oy + size - 1);
    float wy = yf - (float)y0;

    // x coordinate
    float tx = ((float)xs + 0.5f) * sc - 0.5f;
    float xf = (float)ox + tx;
    xf = fminf(fmaxf(xf, (float)ox), (float)ox + s - 1.0f);
    int   x0 = (int)floorf(xf);
    int   x1 = min(x0 + 1, ox + size - 1);
    float wx = xf - (float)x0;

    const size_t r0 = (size_t)y0 * W;
    const size_t r1 = (size_t)y1 * W;

    float v[3];
#pragma unroll
    for (int c = 0; c < 3; ++c) {
        const float* base = img + (size_t)c * CH_STRIDE;
        const float v00 = __ldg(base + r0 + x0);
        const float v01 = __ldg(base + r0 + x1);
        const float v10 = __ldg(base + r1 + x0);
        const float v11 = __ldg(base + r1 + x1);
        const float top = v00 * (1.0f - wx) + v01 * wx;
        const float bot = v10 * (1.0f - wx) + v11 * wx;
        v[c] = top * (1.0f - wy) + bot * wy;
    }

    if (gray) {
        const float g = 0.2989f * v[0] + 0.587f * v[1] + 0.114f * v[2];
        v[0] = g; v[1] = g; v[2] = g;
    }

    const size_t obase = ((size_t)im * 3) * (CUT * CUT) + (size_t)yo * CUT + xo;
#pragma unroll
    for (int c = 0; c < 3; ++c)
        out[obase + (size_t)c * (CUT * CUT)] = v[c];
}

extern "C" void kernel_launch(void* const* d_in, const int* in_sizes, int n_in,
                              void* d_out, int out_size)
{
    const float* img   = (const float*)d_in[0];
    // d_in[1] = t (unused)
    const int*   sizes = (const int*)d_in[2];
    const int*   offy  = (const int*)d_in[3];
    const int*   offx  = (const int*)d_in[4];
    float*       out   = (float*)d_out;

    dim3 block(256, 1, 1);
    dim3 grid((CUT * CUT) / 256, 16, 1);
    dango_cutouts_kernel<<<grid, block>>>(img, sizes, offy, offx, out);
}

// round 2
// speedup vs baseline: 1.1855x; 1.1855x over previous
#include <cuda_runtime.h>
#include <cstdint>

// DangoCutouts: 16 x (3,512,512) fp32 outputs from one (3,4096,4096) image.
// Images 0-3 (full downsample: color / gray / flip / gray-flip) all derive
// from ONE bilinear gather -> computed once, written 4x (12 planes).
// Images 4..15: random crops (offy/offx/sizes), crop 0 grayed.

#define H 4096
#define W 4096
#define CUT 512
#define CH_STRIDE (4096u * 4096u)
#define PLANE (CUT * CUT)

__device__ __forceinline__ void bilinear3(const float* __restrict__ img,
                                          int oy, int ox, int size,
                                          int yo, int xo, float v[3])
{
    const float s  = (float)size;
    const float sc = s * (1.0f / 512.0f);   // exact power-of-two scale

    float yf = (float)oy + (((float)yo + 0.5f) * sc - 0.5f);
    yf = fminf(fmaxf(yf, (float)oy), (float)oy + s - 1.0f);
    int   y0 = (int)floorf(yf);
    int   y1 = min(y0 + 1, oy + size - 1);
    float wy = yf - (float)y0;

    float xf = (float)ox + (((float)xo + 0.5f) * sc - 0.5f);
    xf = fminf(fmaxf(xf, (float)ox), (float)ox + s - 1.0f);
    int   x0 = (int)floorf(xf);
    int   x1 = min(x0 + 1, ox + size - 1);
    float wx = xf - (float)x0;

    const size_t r0 = (size_t)y0 * W;
    const size_t r1 = (size_t)y1 * W;

#pragma unroll
    for (int c = 0; c < 3; ++c) {
        const float* base = img + (size_t)c * CH_STRIDE;
        const float v00 = __ldg(base + r0 + x0);
        const float v01 = __ldg(base + r0 + x1);
        const float v10 = __ldg(base + r1 + x0);
        const float v11 = __ldg(base + r1 + x1);
        const float top = v00 + (v01 - v00) * wx;
        const float bot = v10 + (v11 - v10) * wx;
        v[c] = top + (bot - top) * wy;
    }
}

__global__ __launch_bounds__(256)
void dango_cutouts_kernel(const float* __restrict__ img,
                          const int*   __restrict__ sizes,
                          const int*   __restrict__ offy,
                          const int*   __restrict__ offx,
                          float*       __restrict__ out)
{
    const int p  = blockIdx.x * blockDim.x + threadIdx.x;   // 0 .. 512*512-1
    const int g  = blockIdx.y;                               // 0 .. 12
    const int yo = p >> 9;
    const int xo = p & 511;

    float v[3];

    if (g == 0) {
        // One gather serves images 0,1,2,3.
        bilinear3(img, 0, 0, 4096, yo, xo, v);
        const float gr = 0.2989f * v[0] + 0.587f * v[1] + 0.114f * v[2];

        const size_t row = (size_t)yo * CUT;
        const size_t pf  = row + xo;            // forward pixel
        const size_t pr  = row + (511 - xo);    // flipped pixel
#pragma unroll
        for (int c = 0; c < 3; ++c) {
            const size_t cp = (size_t)c * PLANE;
            out[ 0 * PLANE + cp + pf] = v[c];   // img0: full
            out[ 3 * PLANE + cp + pf] = gr;     // img1: gray(full)
            out[ 6 * PLANE + cp + pr] = v[c];   // img2: flipped
            out[ 9 * PLANE + cp + pr] = gr;     // img3: gray(flipped)
        }
    } else {
        const int j  = g - 1;                   // crop index 0..11
        const int oy = __ldg(offy  + j);
        const int ox = __ldg(offx  + j);
        const int sz = __ldg(sizes + j);

        bilinear3(img, oy, ox, sz, yo, xo, v);

        if (j == 0) {
            const float gr = 0.2989f * v[0] + 0.587f * v[1] + 0.114f * v[2];
            v[0] = gr; v[1] = gr; v[2] = gr;
        }

        const size_t obase = ((size_t)(j + 4) * 3) * PLANE + (size_t)yo * CUT + xo;
#pragma unroll
        for (int c = 0; c < 3; ++c)
            out[obase + (size_t)c * PLANE] = v[c];
    }
}

extern "C" void kernel_launch(void* const* d_in, const int* in_sizes, int n_in,
                              void* d_out, int out_size)
{
    const float* img   = (const float*)d_in[0];
    // d_in[1] = t (unused)
    const int*   sizes = (const int*)d_in[2];
    const int*   offy  = (const int*)d_in[3];
    const int*   offx  = (const int*)d_in[4];
    float*       out   = (float*)d_out;

    dim3 block(256, 1, 1);
    dim3 grid(PLANE / 256, 13, 1);
    dango_cutouts_kernel<<<grid, block>>>(img, sizes, offy, offx, out);
}